// round 17
// baseline (speedup 1.0000x reference)
#include <cuda_runtime.h>
#include <cuda_fp16.h>
#include <math.h>
#include <stdint.h>

// ---------------- problem constants ----------------
constexpr int B_  = 8;
constexpr int B2  = 16;
constexpr int NN  = 2000;
constexpr int E_  = 512;
constexpr int HEN = 1024;
constexpr int D_  = 128;
constexpr int HD  = 512;
constexpr int KF  = 4096;
constexpr int IB_ = 64;
constexpr long long MR  = (long long)B_ * NN;   // 16000
constexpr long long MR2 = (long long)B2 * NN;   // 32000

constexpr int ROWCAP = 64;
constexpr int CAP    = 131072;

// ---------------- scratch layout ----------------
constexpr long long SZ_AGH  = MR2 * E_ / 2;
constexpr long long SZ_HENH = MR2 * HEN / 2;
constexpr long long SZ_HH   = MR2 * D_ / 2;
constexpr long long SZ_GLWT = (long long)KF * D_ / 2;
constexpr long long SZ_FH   = MR2 * KF / 2;
constexpr long long SZ_ATT  = (long long)B2 * NN * NN;
constexpr long long SZ_DINV = MR2;
constexpr long long SZ_TH   = MR2 * HD / 2;
constexpr long long SZ_OH   = MR2 * HD / 2;
constexpr long long SZ_O3   = MR2 * D_;
constexpr long long SZ_Z    = (long long)B2 * IB_;
constexpr long long SZ_W1T  = (long long)HEN * E_ / 2;
constexpr long long SZ_W2T  = (long long)D_ * HEN / 2;
constexpr long long SZ_GW1T = (long long)HD * D_ / 2;
constexpr long long SZ_GW2T = (long long)HD * HD / 2;
constexpr long long SZ_GW3T = (long long)D_ * HD / 2;
constexpr long long SZ_ROWV = MR2 * ROWCAP;
constexpr long long SZ_ROWC = MR2 * ROWCAP;
constexpr long long SZ_RCNT = MR2;
constexpr long long SZ_CCNT = MR2;
constexpr long long SZ_COFF = MR2;
constexpr long long SZ_CCUR = MR2;
constexpr long long SZ_CSUM = MR2;
constexpr long long SZ_CSCV = (long long)B2 * CAP;
constexpr long long SZ_CSCR = (long long)B2 * CAP;

constexpr long long OFF_AGH  = 0;
constexpr long long OFF_HENH = OFF_AGH + SZ_AGH;
constexpr long long OFF_HH   = OFF_HENH + SZ_HENH;
constexpr long long OFF_GLWT = OFF_HH + SZ_HH;
constexpr long long OFF_FH   = OFF_GLWT + SZ_GLWT;
constexpr long long OFF_ATT  = OFF_FH + SZ_FH;
constexpr long long OFF_DINV = OFF_ATT + SZ_ATT;
constexpr long long OFF_TH   = OFF_DINV + SZ_DINV;
constexpr long long OFF_O1H  = OFF_TH + SZ_TH;
constexpr long long OFF_O2H  = OFF_O1H + SZ_OH;
constexpr long long OFF_O3   = OFF_O2H + SZ_OH;
constexpr long long OFF_Z    = OFF_O3 + SZ_O3;
constexpr long long OFF_W1T  = OFF_Z + SZ_Z;
constexpr long long OFF_W2T  = OFF_W1T + SZ_W1T;
constexpr long long OFF_GW1T = OFF_W2T + SZ_W2T;
constexpr long long OFF_GW2T = OFF_GW1T + SZ_GW1T;
constexpr long long OFF_GW3T = OFF_GW2T + SZ_GW2T;
constexpr long long OFF_ROWV = OFF_GW3T + SZ_GW3T;
constexpr long long OFF_ROWC = OFF_ROWV + SZ_ROWV;
constexpr long long OFF_RCNT = OFF_ROWC + SZ_ROWC;
constexpr long long OFF_CCNT = OFF_RCNT + SZ_RCNT;
constexpr long long OFF_COFF = OFF_CCNT + SZ_CCNT;
constexpr long long OFF_CCUR = OFF_COFF + SZ_COFF;
constexpr long long OFF_CSUM = OFF_CCUR + SZ_CCUR;
constexpr long long OFF_CSCV = OFF_CSUM + SZ_CSUM;
constexpr long long OFF_CSCR = OFF_CSCV + SZ_CSCV;
constexpr long long SCRATCH_TOTAL = OFF_CSCR + SZ_CSCR;

__device__ float g_scratch[SCRATCH_TOTAL];

// ---------------- helpers ----------------
__device__ __forceinline__ void mma_f16(float* c, const uint32_t* a, uint32_t b0, uint32_t b1) {
    asm volatile(
        "mma.sync.aligned.m16n8k16.row.col.f32.f16.f16.f32 "
        "{%0,%1,%2,%3}, {%4,%5,%6,%7}, {%8,%9}, {%0,%1,%2,%3};"
        : "+f"(c[0]), "+f"(c[1]), "+f"(c[2]), "+f"(c[3])
        : "r"(a[0]), "r"(a[1]), "r"(a[2]), "r"(a[3]), "r"(b0), "r"(b1));
}

__device__ __forceinline__ void ldsm4(uint32_t* r, uint32_t addr) {
    asm volatile("ldmatrix.sync.aligned.m8n8.x4.shared.b16 {%0,%1,%2,%3}, [%4];"
                 : "=r"(r[0]), "=r"(r[1]), "=r"(r[2]), "=r"(r[3]) : "r"(addr));
}

__device__ __forceinline__ void cpa16(uint32_t dst, const void* src, bool pred) {
    int sz = pred ? 16 : 0;
    asm volatile("cp.async.cg.shared.global [%0], [%1], 16, %2;\n"
                 :: "r"(dst), "l"(src), "r"(sz));
}
__device__ __forceinline__ void cpa_commit() { asm volatile("cp.async.commit_group;\n"); }
__device__ __forceinline__ void cpa_wait1()  { asm volatile("cp.async.wait_group 1;\n"); }

__device__ __forceinline__ uint32_t smem_u32(const void* p) {
    uint32_t a;
    asm("{ .reg .u64 t; cvta.to.shared.u64 t, %1; cvt.u32.u64 %0, t; }" : "=r"(a) : "l"(p));
    return a;
}

constexpr int PK = 20;
constexpr int ASTG = 2560;
constexpr int BSTG = 2560;
constexpr int SMEM_BYTES = (3 * ASTG + 3 * BSTG) * 4;   // 61440

// ================= unified fp16 GEMM =================
template<int ACT, int EPI, int OUTH>
__global__ void __launch_bounds__(256, 2) hgemm_k(
    int M, int N, int K,
    const __half* __restrict__ A,
    const __half* __restrict__ Bt,
    void* __restrict__ C, int ldc,
    const float* __restrict__ bias,
    const float* __restrict__ dinv)
{
    extern __shared__ uint32_t sh[];
    const int bn = blockIdx.x, bm = blockIdx.y;
    const int m0 = bm * 128, n0 = bn * 128;

    const int tid  = threadIdx.x;
    const int lane = tid & 31, warp = tid >> 5;
    const int g = lane >> 2, th = lane & 3;
    const int wm = (warp >> 1) * 32;
    const int wn = (warp & 1) * 64;
    const int r8 = lane & 7, sel = lane >> 3;

    uint32_t sbase = smem_u32(sh);

    float acc[2][8][4];
#pragma unroll
    for (int i = 0; i < 2; i++)
#pragma unroll
        for (int j = 0; j < 8; j++)
#pragma unroll
            for (int l = 0; l < 4; l++) acc[i][j][l] = 0.f;

    const int KT = K / 32;

    auto issue = [&](int kt, int stg) {
        uint32_t abase = sbase + (uint32_t)(stg * ASTG) * 4u;
        uint32_t bbase = sbase + (uint32_t)(3 * ASTG + stg * BSTG) * 4u;
#pragma unroll
        for (int it = 0; it < 2; it++) {
            int c = tid * 2 + it;
            int row = c >> 2, kc = c & 3;
            const __half* srcA = A + (long long)(m0 + row) * K + kt * 32 + kc * 8;
            cpa16(abase + (uint32_t)(row * PK + kc * 4) * 4u, srcA, (m0 + row) < M);
            const __half* srcB = Bt + (long long)(n0 + row) * K + kt * 32 + kc * 8;
            cpa16(bbase + (uint32_t)(row * PK + kc * 4) * 4u, srcB, (n0 + row) < N);
        }
    };

    auto mmaTile = [&](int stg) {
        uint32_t abase = sbase + (uint32_t)(stg * ASTG) * 4u;
        uint32_t bbase = sbase + (uint32_t)(3 * ASTG + stg * BSTG) * 4u;
#pragma unroll
        for (int s = 0; s < 2; s++) {
            const int k0 = s * 8;
            uint32_t a[2][4];
#pragma unroll
            for (int mt = 0; mt < 2; mt++) {
                int row = wm + mt * 16 + ((sel & 1) << 3) + r8;
                int ku  = k0 + ((sel & 2) << 1);
                ldsm4(a[mt], abase + (uint32_t)(row * PK + ku) * 4u);
            }
            uint32_t b0v[8], b1v[8];
#pragma unroll
            for (int g4 = 0; g4 < 2; g4++) {
                int row = wn + g4 * 32 + sel * 8 + r8;
                ldsm4(&b0v[g4 * 4], bbase + (uint32_t)(row * PK + k0) * 4u);
                ldsm4(&b1v[g4 * 4], bbase + (uint32_t)(row * PK + k0 + 4) * 4u);
            }
#pragma unroll
            for (int nt = 0; nt < 8; nt++) {
                mma_f16(acc[0][nt], a[0], b0v[nt], b1v[nt]);
                mma_f16(acc[1][nt], a[1], b0v[nt], b1v[nt]);
            }
        }
    };

    issue(0, 0); cpa_commit();
    if (KT > 1) issue(1, 1);
    cpa_commit();
    cpa_wait1();
    __syncthreads();

    for (int kt = 0; kt < KT; kt++) {
        int stg = kt % 3;
        if (kt + 2 < KT) issue(kt + 2, (kt + 2) % 3);
        cpa_commit();
        mmaTile(stg);
        cpa_wait1();
        __syncthreads();
    }

    __half* Ch = (__half*)C;
    float*  Cf = (float*)C;
#pragma unroll
    for (int mt = 0; mt < 2; mt++) {
#pragma unroll
        for (int nt = 0; nt < 8; nt++) {
#pragma unroll
            for (int eh = 0; eh < 2; eh++) {
                int gm = m0 + wm + mt * 16 + g + (eh ? 8 : 0);
                int gn = n0 + wn + nt * 8 + 2 * th;
                if (gm >= M || gn >= N) continue;
                float v0 = acc[mt][nt][eh * 2 + 0];
                float v1 = acc[mt][nt][eh * 2 + 1];
                if (EPI == 1) { float dv = dinv[gm]; v0 *= dv; v1 *= dv; }
                if (bias)     { v0 += bias[gn]; v1 += bias[gn + 1]; }
                if (ACT == 1) { v0 = fmaxf(v0, 0.f); v1 = fmaxf(v1, 0.f); }
                if (ACT == 2) {
                    v0 = 0.5f * v0 * (1.f + erff(v0 * 0.70710678118654752f));
                    v1 = 0.5f * v1 * (1.f + erff(v1 * 0.70710678118654752f));
                }
                if (OUTH) {
                    *reinterpret_cast<__half2*>(&Ch[(long long)gm * ldc + gn]) =
                        __floats2half2_rn(v0, v1);
                } else {
                    Cf[(long long)gm * ldc + gn]     = v0;
                    Cf[(long long)gm * ldc + gn + 1] = v1;
                }
            }
        }
    }
}

// ---------------- fp16 gram, fp32 att; coalesced mirror via smem transpose ----------------
__global__ void __launch_bounds__(256, 2) hgram_k(const __half* __restrict__ F,
                                                  float* __restrict__ att)
{
    extern __shared__ uint32_t sh[];
    const int bn = blockIdx.x, bm = blockIdx.y, b = blockIdx.z;
    if (bm > bn) return;
    const int m0 = bm * 128, n0 = bn * 128;

    const int tid  = threadIdx.x;
    const int lane = tid & 31, warp = tid >> 5;
    const int g = lane >> 2, th = lane & 3;
    const int wm = (warp >> 1) * 32;
    const int wn = (warp & 1) * 64;
    const int r8 = lane & 7, sel = lane >> 3;

    uint32_t sbase = smem_u32(sh);
    const __half* Fb = F + (long long)b * NN * KF;
    float* attb = att + (long long)b * NN * NN;

    float acc[2][8][4];
#pragma unroll
    for (int i = 0; i < 2; i++)
#pragma unroll
        for (int j = 0; j < 8; j++)
#pragma unroll
            for (int l = 0; l < 4; l++) acc[i][j][l] = 0.f;

    const int KT = KF / 32;

    auto issue = [&](int kt, int stg) {
        uint32_t abase = sbase + (uint32_t)(stg * ASTG) * 4u;
        uint32_t bbase = sbase + (uint32_t)(3 * ASTG + stg * BSTG) * 4u;
#pragma unroll
        for (int it = 0; it < 2; it++) {
            int c = tid * 2 + it;
            int row = c >> 2, kc = c & 3;
            const __half* srcA = Fb + (long long)(m0 + row) * KF + kt * 32 + kc * 8;
            cpa16(abase + (uint32_t)(row * PK + kc * 4) * 4u, srcA, (m0 + row) < NN);
            const __half* srcB = Fb + (long long)(n0 + row) * KF + kt * 32 + kc * 8;
            cpa16(bbase + (uint32_t)(row * PK + kc * 4) * 4u, srcB, (n0 + row) < NN);
        }
    };

    auto mmaTile = [&](int stg) {
        uint32_t abase = sbase + (uint32_t)(stg * ASTG) * 4u;
        uint32_t bbase = sbase + (uint32_t)(3 * ASTG + stg * BSTG) * 4u;
#pragma unroll
        for (int s = 0; s < 2; s++) {
            const int k0 = s * 8;
            uint32_t a[2][4];
#pragma unroll
            for (int mt = 0; mt < 2; mt++) {
                int row = wm + mt * 16 + ((sel & 1) << 3) + r8;
                int ku  = k0 + ((sel & 2) << 1);
                ldsm4(a[mt], abase + (uint32_t)(row * PK + ku) * 4u);
            }
            uint32_t b0v[8], b1v[8];
#pragma unroll
            for (int g4 = 0; g4 < 2; g4++) {
                int row = wn + g4 * 32 + sel * 8 + r8;
                ldsm4(&b0v[g4 * 4], bbase + (uint32_t)(row * PK + k0) * 4u);
                ldsm4(&b1v[g4 * 4], bbase + (uint32_t)(row * PK + k0 + 4) * 4u);
            }
#pragma unroll
            for (int nt = 0; nt < 8; nt++) {
                mma_f16(acc[0][nt], a[0], b0v[nt], b1v[nt]);
                mma_f16(acc[1][nt], a[1], b0v[nt], b1v[nt]);
            }
        }
    };

    issue(0, 0); cpa_commit();
    if (KT > 1) issue(1, 1);
    cpa_commit();
    cpa_wait1();
    __syncthreads();

    for (int kt = 0; kt < KT; kt++) {
        int stg = kt % 3;
        if (kt + 2 < KT) issue(kt + 2, (kt + 2) % 3);
        cpa_commit();
        mmaTile(stg);
        cpa_wait1();
        __syncthreads();
    }

    // direct stores (float2)
#pragma unroll
    for (int mt = 0; mt < 2; mt++) {
#pragma unroll
        for (int nt = 0; nt < 8; nt++) {
#pragma unroll
            for (int eh = 0; eh < 2; eh++) {
                int gm = m0 + wm + mt * 16 + g + (eh ? 8 : 0);
                int gn = n0 + wn + nt * 8 + 2 * th;
                if (gm >= NN || gn + 1 >= NN) continue;
                float2 v = make_float2(0.125f * acc[mt][nt][eh * 2 + 0],
                                       0.125f * acc[mt][nt][eh * 2 + 1]);
                *reinterpret_cast<float2*>(&attb[(long long)gm * NN + gn]) = v;
            }
        }
    }

    // mirror via smem transpose (coalesced)
    if (bm < bn) {
        float* smf = reinterpret_cast<float*>(sh);
#pragma unroll
        for (int p = 0; p < 2; p++) {
            if ((warp & 1) == p) {
#pragma unroll
                for (int mt = 0; mt < 2; mt++) {
#pragma unroll
                    for (int nt = 0; nt < 8; nt++) {
#pragma unroll
                        for (int eh = 0; eh < 2; eh++) {
                            int gml  = wm + mt * 16 + g + (eh ? 8 : 0);
                            int rowl = nt * 8 + 2 * th;
                            smf[rowl * 132 + gml]       = 0.125f * acc[mt][nt][eh * 2 + 0];
                            smf[(rowl + 1) * 132 + gml] = 0.125f * acc[mt][nt][eh * 2 + 1];
                        }
                    }
                }
            }
            __syncthreads();
            for (int idx = tid; idx < 2048; idx += 256) {
                int rowl = idx >> 5, c4 = (idx & 31) << 2;
                int gn = n0 + p * 64 + rowl;
                if (gn < NN && m0 + c4 + 3 < NN) {
                    float4 v = *reinterpret_cast<float4*>(&smf[rowl * 132 + c4]);
                    *reinterpret_cast<float4*>(&attb[(long long)gn * NN + m0 + c4]) = v;
                }
            }
            __syncthreads();
        }
    }
}

// ---------------- weight transpose to half ----------------
__global__ void trhalf_k(const float* __restrict__ src, __half* __restrict__ dst, int K, int N)
{
    int idx = blockIdx.x * blockDim.x + threadIdx.x;
    if (idx >= K * N) return;
    int n = idx / K, k = idx % K;
    dst[(long long)n * K + k] = __float2half_rn(src[(long long)k * N + n]);
}

// ---------------- gl_w -> GLWt half [KF, D] ----------------
__global__ void glwt_k(const float* __restrict__ glw, __half* __restrict__ GLWt)
{
    int idx = blockIdx.x * blockDim.x + threadIdx.x;
    if (idx >= KF * D_) return;
    int c = idx / D_, k = idx % D_;
    int p = c >> 9, hh = c & 511;
    GLWt[idx] = __float2half_rn(glw[((long long)p * D_ + k) * HD + hh]);
}

// ---------------- A-matrix builder (both views) ----------------
__global__ void build_ag2_k(const float* __restrict__ x1, const float* __restrict__ x2,
                            const float* __restrict__ emb,
                            const float* __restrict__ gw, const float* __restrict__ gb,
                            __half* __restrict__ Ag)
{
    long long idx = (long long)blockIdx.x * blockDim.x + threadIdx.x;
    if (idx >= MR2 * E_) return;
    int e = (int)(idx & (E_ - 1));
    long long r = idx >> 9;
    long long rv = (r < MR) ? r : r - MR;
    const float* x = (r < MR) ? x1 : x2;
    int n = (int)(rv % NN);
    float t = fmaf(x[rv], gw[e], gb[e]);
    float sgm = 1.0f / (1.0f + expf(-t));
    Ag[idx] = __float2half_rn(sgm * emb[(long long)n * E_ + e]);
}

// ---------------- top-k(50): register-resident, fp32 att ----------------
__global__ void __launch_bounds__(256) topk_rows_k(
    const float* __restrict__ att,
    float* __restrict__ rowval, int* __restrict__ rowcol, int* __restrict__ rowcnt)
{
    __shared__ int   hist[256];
    __shared__ float wredf[8];
    __shared__ float s_bcast;
    __shared__ int   s_selb, s_selk, s_pos;

    long long row = blockIdx.x;
    const float* r = att + row * 2000;
    int tid = threadIdx.x;
    int lane = tid & 31, wid = tid >> 5;

    float v[8];
#pragma unroll
    for (int p = 0; p < 8; p++) {
        int i = tid + p * 256;
        v[p] = (i < 2000) ? r[i] : 0.f;
    }
    if (tid == 0) s_pos = 0;

    float mx = 0.f;
#pragma unroll
    for (int p = 0; p < 8; p++) mx = fmaxf(mx, v[p]);
#pragma unroll
    for (int o = 16; o; o >>= 1) mx = fmaxf(mx, __shfl_xor_sync(0xffffffffu, mx, o));
    if (lane == 0) wredf[wid] = mx;
    __syncthreads();
    if (tid == 0) { float m = wredf[0]; for (int w = 1; w < 8; w++) m = fmaxf(m, wredf[w]); s_bcast = m; }
    __syncthreads();
    mx = s_bcast;

    unsigned prefix = 0u;
    int k = 50;
#pragma unroll
    for (int pass = 0; pass < 4; pass++) {
        const int shift = 24 - 8 * pass;
        const unsigned hmask = (pass == 0) ? 0u : (0xFFFFFFFFu << (shift + 8));
        if (tid < 256) hist[tid] = 0;
        __syncthreads();
#pragma unroll
        for (int p = 0; p < 8; p++) {
            int i = tid + p * 256;
            if (i < 2000) {
                unsigned u = __float_as_uint(v[p]);
                if ((u & hmask) == prefix)
                    atomicAdd(&hist[(u >> shift) & 255], 1);
            }
        }
        __syncthreads();
        if (tid == 0) {
            int acc = 0, b = 255;
            for (; b > 0; b--) { acc += hist[b]; if (acc >= k) break; }
            if (acc < k) acc += hist[0];
            s_selb = b;
            s_selk = k - (acc - hist[b]);
        }
        __syncthreads();
        prefix |= ((unsigned)s_selb) << shift;
        k = s_selk;
        __syncthreads();
    }
    float thr = __uint_as_float(prefix);

    float sum = 0.f;
#pragma unroll
    for (int p = 0; p < 8; p++) {
        int i = tid + p * 256;
        if (i < 2000 && v[p] >= thr) sum += expf(v[p] - mx);
    }
#pragma unroll
    for (int o = 16; o; o >>= 1) sum += __shfl_xor_sync(0xffffffffu, sum, o);
    if (lane == 0) wredf[wid] = sum;
    __syncthreads();
    if (tid == 0) { float t = 0.f; for (int w = 0; w < 8; w++) t += wredf[w]; s_bcast = t; }
    __syncthreads();
    float inv = 1.0f / s_bcast;

#pragma unroll
    for (int p = 0; p < 8; p++) {
        int i = tid + p * 256;
        if (i < 2000 && v[p] >= thr) {
            int pos = atomicAdd(&s_pos, 1);
            if (pos < ROWCAP) {
                rowval[row * ROWCAP + pos] = expf(v[p] - mx) * inv;
                rowcol[row * ROWCAP + pos] = i;
            }
        }
    }
    __syncthreads();
    if (tid == 0) rowcnt[row] = min(s_pos, ROWCAP);
}

// ---------------- zero ----------------
__global__ void zero_k(int* __restrict__ a, float* __restrict__ b, int n)
{
    int i = blockIdx.x * blockDim.x + threadIdx.x;
    if (i < n) { a[i] = 0; b[i] = 0.f; }
}

// ---------------- count column occupancy ----------------
__global__ void count_k(const int* __restrict__ rowcol, const int* __restrict__ rowcnt,
                        int* __restrict__ colcnt)
{
    int row = blockIdx.x;
    int b = row / NN;
    int cnt = rowcnt[row];
    if (threadIdx.x < cnt)
        atomicAdd(&colcnt[b * NN + rowcol[row * ROWCAP + threadIdx.x]], 1);
}

// ---------------- per-batch exclusive scan ----------------
__global__ void __launch_bounds__(256) scan_k(const int* __restrict__ colcnt,
                                              int* __restrict__ coloff, int* __restrict__ colcur)
{
    __shared__ int tsum[257];
    int b = blockIdx.x, tid = threadIdx.x;
    const int* cnt = colcnt + b * NN;
    int local[8];
    int tot = 0;
#pragma unroll
    for (int e = 0; e < 8; e++) {
        int i = tid * 8 + e;
        local[e] = tot;
        tot += (i < NN) ? cnt[i] : 0;
    }
    tsum[tid] = tot;
    __syncthreads();
    if (tid == 0) {
        int acc = 0;
        for (int t = 0; t < 256; t++) { int v = tsum[t]; tsum[t] = acc; acc += v; }
    }
    __syncthreads();
    int base = tsum[tid];
#pragma unroll
    for (int e = 0; e < 8; e++) {
        int i = tid * 8 + e;
        if (i < NN) {
            coloff[b * NN + i] = base + local[e];
            colcur[b * NN + i] = base + local[e];
        }
    }
}

// ---------------- place into CSC ----------------
__global__ void place_k(const float* __restrict__ rowval, const int* __restrict__ rowcol,
                        const int* __restrict__ rowcnt,
                        int* __restrict__ colcur, float* __restrict__ colsum,
                        float* __restrict__ cscval, int* __restrict__ cscrow)
{
    int row = blockIdx.x;
    int b = row / NN, j = row % NN;
    int cnt = rowcnt[row];
    int e = threadIdx.x;
    if (e < cnt) {
        int   c = rowcol[row * ROWCAP + e];
        float w = rowval[row * ROWCAP + e];
        int pos = atomicAdd(&colcur[b * NN + c], 1);
        cscval[(long long)b * CAP + pos] = w;
        cscrow[(long long)b * CAP + pos] = j;
        atomicAdd(&colsum[b * NN + c], w);
    }
}

// ---------------- dinv ----------------
__global__ void dinv_k(const float* __restrict__ colsum, float* __restrict__ dinv, int n)
{
    int i = blockIdx.x * blockDim.x + threadIdx.x;
    if (i < n) dinv[i] = rsqrtf(1.0f + colsum[i]);
}

// ---------------- sparse GCN aggregation, ILP-4 gather ----------------
template<int DIM, int ACT, int OUTH>
__global__ void spagg_k(
    const float* __restrict__ cscval, const int* __restrict__ cscrow,
    const int* __restrict__ coloff, const int* __restrict__ colcnt,
    const __half* __restrict__ T, const float* __restrict__ dinv,
    const float* __restrict__ bias, void* __restrict__ out)
{
    __shared__ float sw[256];
    __shared__ int   sj[256];
    int i = blockIdx.x, b = blockIdx.y, tid = threadIdx.x;
    const __half* Tb = T + (long long)b * NN * DIM;
    int s0  = coloff[b * NN + i];
    int cnt = colcnt[b * NN + i];
    long long base = (long long)b * CAP + s0;

    float2 a0 = __half22float2(*reinterpret_cast<const __half2*>(&Tb[(long long)i * DIM + 2 * tid]));
    float2 a1 = make_float2(0.f, 0.f);
    float2 a2 = make_float2(0.f, 0.f);
    float2 a3 = make_float2(0.f, 0.f);

    for (int e0 = 0; e0 < cnt; e0 += blockDim.x) {
        int chunk = min(cnt - e0, (int)blockDim.x);
        if (tid < chunk) {
            sw[tid] = cscval[base + e0 + tid];
            sj[tid] = cscrow[base + e0 + tid];
        }
        __syncthreads();
        int e = 0;
        for (; e + 3 < chunk; e += 4) {
            float2 t0 = __half22float2(*reinterpret_cast<const __half2*>(&Tb[(long long)sj[e]   * DIM + 2 * tid]));
            float2 t1 = __half22float2(*reinterpret_cast<const __half2*>(&Tb[(long long)sj[e+1] * DIM + 2 * tid]));
            float2 t2 = __half22float2(*reinterpret_cast<const __half2*>(&Tb[(long long)sj[e+2] * DIM + 2 * tid]));
            float2 t3 = __half22float2(*reinterpret_cast<const __half2*>(&Tb[(long long)sj[e+3] * DIM + 2 * tid]));
            a0.x = fmaf(sw[e],   t0.x, a0.x); a0.y = fmaf(sw[e],   t0.y, a0.y);
            a1.x = fmaf(sw[e+1], t1.x, a1.x); a1.y = fmaf(sw[e+1], t1.y, a1.y);
            a2.x = fmaf(sw[e+2], t2.x, a2.x); a2.y = fmaf(sw[e+2], t2.y, a2.y);
            a3.x = fmaf(sw[e+3], t3.x, a3.x); a3.y = fmaf(sw[e+3], t3.y, a3.y);
        }
        for (; e < chunk; e++) {
            float2 t0 = __half22float2(*reinterpret_cast<const __half2*>(&Tb[(long long)sj[e] * DIM + 2 * tid]));
            a0.x = fmaf(sw[e], t0.x, a0.x);
            a0.y = fmaf(sw[e], t0.y, a0.y);
        }
        __syncthreads();
    }
    float dv = dinv[b * NN + i];
    float vx = dv * ((a0.x + a1.x) + (a2.x + a3.x)) + bias[2 * tid];
    float vy = dv * ((a0.y + a1.y) + (a2.y + a3.y)) + bias[2 * tid + 1];
    if (ACT == 1) { vx = fmaxf(vx, 0.f); vy = fmaxf(vy, 0.f); }
    if (OUTH) {
        __half* oh = (__half*)out;
        *reinterpret_cast<__half2*>(&oh[((long long)b * NN + i) * DIM + 2 * tid]) =
            __floats2half2_rn(vx, vy);
    } else {
        float* of = (float*)out;
        *reinterpret_cast<float2*>(&of[((long long)b * NN + i) * DIM + 2 * tid]) = make_float2(vx, vy);
    }
}

// ---------------- per-view mean over nodes; mu/std/z ----------------
__global__ void meanz1_k(const float* __restrict__ O3, const float* __restrict__ eps,
                         float* __restrict__ mu, float* __restrict__ stdv,
                         float* __restrict__ z)
{
    int b = blockIdx.x, d = threadIdx.x;
    const float* p = O3 + ((long long)b * 2000) * 128 + d;
    float s0 = 0.f, s1 = 0.f, s2 = 0.f, s3 = 0.f;
    for (int i = 0; i < 2000; i += 4) {
        s0 += p[(long long)i * 128];
        s1 += p[(long long)(i + 1) * 128];
        s2 += p[(long long)(i + 2) * 128];
        s3 += p[(long long)(i + 3) * 128];
    }
    __shared__ float sg[128];
    sg[d] = ((s0 + s1) + (s2 + s3)) / 2000.0f;
    __syncthreads();
    if (d < 64) {
        float m = sg[d];
        float sp = log1pf(expf(sg[64 + d] - 64.0f));
        mu[b * 64 + d] = m;
        stdv[b * 64 + d] = sp;
        z[b * 64 + d] = fmaf(eps[b * 64 + d], sp, m);
    }
}

// ---------------- decoder ----------------
__global__ void __launch_bounds__(256) decode_k(
    const float* __restrict__ z, const float* __restrict__ w1, const float* __restrict__ b1,
    const float* __restrict__ gamma, const float* __restrict__ beta,
    const float* __restrict__ w2, const float* __restrict__ b2,
    float* __restrict__ xrec)
{
    __shared__ float h[1024];
    __shared__ float zs[64];
    int b = blockIdx.x, tid = threadIdx.x;
    if (tid < 64) zs[tid] = z[b * 64 + tid];
    __syncthreads();
    const float invc = 1.0f / sqrtf(1.0f + 1e-5f);
    for (int c = tid; c < 1024; c += 256) {
        float a = b1[c];
#pragma unroll 8
        for (int k = 0; k < 64; k++) a = fmaf(zs[k], w1[k * 1024 + c], a);
        a = a * (gamma[c] * invc) + beta[c];
        h[c] = fmaxf(a, 0.f);
    }
    __syncthreads();
    int c0 = blockIdx.y * 250;
    int c1 = min(c0 + 250, 2000);
    for (int c = c0 + tid; c < c1; c += 256) {
        float a = b2[c];
        for (int k = 0; k < 1024; k++) a = fmaf(h[k], w2[k * 2000 + c], a);
        xrec[b * 2000 + c] = fmaxf(a, 0.f);
    }
}

// ---------------- host orchestration: pipe-specialized streams ----------------
extern "C" void kernel_launch(void* const* d_in, const int* in_sizes, int n_in,
                              void* d_out, int out_size)
{
    const float* x1     = (const float*)d_in[0];
    const float* x2     = (const float*)d_in[1];
    const float* emb1   = (const float*)d_in[2];
    const float* gate_w = (const float*)d_in[3];
    const float* gate_b = (const float*)d_in[4];
    const float* enc_w1 = (const float*)d_in[5];
    const float* enc_b1 = (const float*)d_in[6];
    const float* enc_w2 = (const float*)d_in[7];
    const float* enc_b2 = (const float*)d_in[8];
    const float* gl_w   = (const float*)d_in[9];
    const float* g_w1   = (const float*)d_in[10];
    const float* g_b1   = (const float*)d_in[11];
    const float* g_w2   = (const float*)d_in[12];
    const float* g_b2   = (const float*)d_in[13];
    const float* g_w3   = (const float*)d_in[14];
    const float* g_b3   = (const float*)d_in[15];
    const float* dW1[2] = {(const float*)d_in[16], (const float*)d_in[22]};
    const float* dB1[2] = {(const float*)d_in[17], (const float*)d_in[23]};
    const float* dG [2] = {(const float*)d_in[18], (const float*)d_in[24]};
    const float* dBe[2] = {(const float*)d_in[19], (const float*)d_in[25]};
    const float* dW2[2] = {(const float*)d_in[20], (const float*)d_in[26]};
    const float* dB2[2] = {(const float*)d_in[21], (const float*)d_in[27]};
    const float* epsA[2]= {(const float*)d_in[28], (const float*)d_in[29]};

    static cudaStream_t s1 = nullptr;
    static cudaEvent_t ev[16];
    static bool attr_done = false;
    if (!attr_done) {
        cudaFuncSetAttribute(hgemm_k<2,0,1>, cudaFuncAttributeMaxDynamicSharedMemorySize, SMEM_BYTES);
        cudaFuncSetAttribute(hgemm_k<0,0,1>, cudaFuncAttributeMaxDynamicSharedMemorySize, SMEM_BYTES);
        cudaFuncSetAttribute(hgemm_k<1,0,1>, cudaFuncAttributeMaxDynamicSharedMemorySize, SMEM_BYTES);
        cudaFuncSetAttribute(hgemm_k<0,1,1>, cudaFuncAttributeMaxDynamicSharedMemorySize, SMEM_BYTES);
        cudaFuncSetAttribute(hgram_k, cudaFuncAttributeMaxDynamicSharedMemorySize, SMEM_BYTES);
        cudaStreamCreateWithFlags(&s1, cudaStreamNonBlocking);
        for (int i = 0; i < 16; i++) cudaEventCreateWithFlags(&ev[i], cudaEventDisableTiming);
        attr_done = true;
    }
    // event ids
    enum { EV_FORK = 0, EV_GRAM0, EV_GRAM1, EV_DINV0, EV_DINV1,
           EV_T1_0, EV_T1_1, EV_O1_0, EV_O1_1, EV_T2_0, EV_T2_1,
           EV_O2_0, EV_O2_1, EV_T3_0, EV_T3_1, EV_JOIN };

    float* sc = nullptr;
    cudaGetSymbolAddress((void**)&sc, g_scratch);
    __half* Agh  = (__half*)(sc + OFF_AGH);
    __half* Henh = (__half*)(sc + OFF_HENH);
    __half* Hh   = (__half*)(sc + OFF_HH);
    __half* GLWt = (__half*)(sc + OFF_GLWT);
    __half* Fh   = (__half*)(sc + OFF_FH);
    float*  att  = sc + OFF_ATT;
    float*  dinv = sc + OFF_DINV;
    __half* Th   = (__half*)(sc + OFF_TH);
    __half* O1h  = (__half*)(sc + OFF_O1H);
    __half* O2h  = (__half*)(sc + OFF_O2H);
    float*  O3   = sc + OFF_O3;
    float*  zb   = sc + OFF_Z;
    __half* W1t  = (__half*)(sc + OFF_W1T);
    __half* W2t  = (__half*)(sc + OFF_W2T);
    __half* GW1t = (__half*)(sc + OFF_GW1T);
    __half* GW2t = (__half*)(sc + OFF_GW2T);
    __half* GW3t = (__half*)(sc + OFF_GW3T);
    float* rowval = sc + OFF_ROWV;
    int*   rowcol = (int*)(sc + OFF_ROWC);
    int*   rowcnt = (int*)(sc + OFF_RCNT);
    int*   colcnt = (int*)(sc + OFF_CCNT);
    int*   coloff = (int*)(sc + OFF_COFF);
    int*   colcur = (int*)(sc + OFF_CCUR);
    float* colsum = sc + OFF_CSUM;
    float* cscval = sc + OFF_CSCV;
    int*   cscrow = (int*)(sc + OFF_CSCR);

    float* out = (float*)d_out;
    float* xrec[2] = {out,          out + 16000};
    float* muo [2] = {out + 32000,  out + 33024};
    float* stdo[2] = {out + 32512,  out + 33536};

    // per-view pointer tables
    __half* Hv[2];  __half* Fv[2];  float* av[2];
    float* rvv[2];  int* rcv[2];  int* rnv[2];
    int* ccv[2];  int* cov[2];  int* cuv[2];  float* csv[2];  float* dvv[2];
    float* vv[2];  int* rv2[2];
    __half* Tv[2];  __half* O1v[2];  __half* O2v[2];  float* O3v[2];
    for (int v = 0; v < 2; v++) {
        long long bo = (long long)v * 8 * NN;
        Hv[v]  = Hh + bo * D_;
        Fv[v]  = Fh + bo * KF;
        av[v]  = att + bo * NN;
        rvv[v] = rowval + bo * ROWCAP;
        rcv[v] = rowcol + bo * ROWCAP;
        rnv[v] = rowcnt + bo;
        ccv[v] = colcnt + bo;
        cov[v] = coloff + bo;
        cuv[v] = colcur + bo;
        csv[v] = colsum + bo;
        dvv[v] = dinv + bo;
        vv[v]  = cscval + (long long)v * 8 * CAP;
        rv2[v] = cscrow + (long long)v * 8 * CAP;
        Tv[v]  = Th + bo * HD;
        O1v[v] = O1h + bo * HD;
        O2v[v] = O2h + bo * HD;
        O3v[v] = O3 + bo * D_;
    }

    // ======== s0 (default): tensor stream ========
    trhalf_k<<<(E_ * HEN + 255) / 256, 256>>>(enc_w1, W1t, E_, HEN);
    trhalf_k<<<(HEN * D_ + 255) / 256, 256>>>(enc_w2, W2t, HEN, D_);
    trhalf_k<<<(D_ * HD + 255) / 256, 256>>>(g_w1, GW1t, D_, HD);
    trhalf_k<<<(HD * HD + 255) / 256, 256>>>(g_w2, GW2t, HD, HD);
    trhalf_k<<<(HD * D_ + 255) / 256, 256>>>(g_w3, GW3t, HD, D_);
    glwt_k<<<(KF * D_ + 255) / 256, 256>>>(gl_w, GLWt);

    build_ag2_k<<<(unsigned)((MR2 * E_ + 255) / 256), 256>>>(x1, x2, emb1, gate_w, gate_b, Agh);
    hgemm_k<2,0,1><<<dim3(HEN / 128, 250), 256, SMEM_BYTES>>>(
        (int)MR2, HEN, E_, Agh, W1t, Henh, HEN, enc_b1, nullptr);
    hgemm_k<0,0,1><<<dim3(1, 250), 256, SMEM_BYTES>>>(
        (int)MR2, D_, HEN, Henh, W2t, Hh, D_, enc_b2, nullptr);
    hgemm_k<1,0,1><<<dim3(KF / 128, 250), 256, SMEM_BYTES>>>(
        (int)MR2, KF, D_, Hh, GLWt, Fh, KF, nullptr, nullptr);

    // grams back-to-back on the tensor stream
    hgram_k<<<dim3(16, 16, 8), 256, SMEM_BYTES>>>(Fv[0], av[0]);
    cudaEventRecord(ev[EV_GRAM0], 0);
    hgram_k<<<dim3(16, 16, 8), 256, SMEM_BYTES>>>(Fv[1], av[1]);
    cudaEventRecord(ev[EV_GRAM1], 0);

    // ======== s1: memory stream — sparse chains per view ========
    for (int v = 0; v < 2; v++) {
        cudaStreamWaitEvent(s1, ev[EV_GRAM0 + v], 0);
        zero_k<<<(8 * NN + 255) / 256, 256, 0, s1>>>(ccv[v], csv[v], 8 * NN);
        topk_rows_k<<<16000, 256, 0, s1>>>(av[v], rvv[v], rcv[v], rnv[v]);
        count_k<<<16000, ROWCAP, 0, s1>>>(rcv[v], rnv[v], ccv[v]);
        scan_k<<<8, 256, 0, s1>>>(ccv[v], cov[v], cuv[v]);
        place_k<<<16000, ROWCAP, 0, s1>>>(rvv[v], rcv[v], rnv[v], cuv[v], csv[v], vv[v], rv2[v]);
        dinv_k<<<(8 * NN + 255) / 256, 256, 0, s1>>>(csv[v], dvv[v], 8 * NN);
        cudaEventRecord(ev[EV_DINV0 + v], s1);
    }

    // ======== ping-pong GCN: T-GEMMs on s0, spaggs on s1 ========
    for (int v = 0; v < 2; v++) {
        cudaStreamWaitEvent(0, ev[EV_DINV0 + v], 0);
        hgemm_k<0,1,1><<<dim3(HD / 128, 125), 256, SMEM_BYTES>>>(
            16000, HD, D_, Hv[v], GW1t, Tv[v], HD, nullptr, dvv[v]);
        cudaEventRecord(ev[EV_T1_0 + v], 0);
    }
    for (int v = 0; v < 2; v++) {
        cudaStreamWaitEvent(s1, ev[EV_T1_0 + v], 0);
        spagg_k<HD,1,1><<<dim3(NN, 8), HD/2, 0, s1>>>(vv[v], rv2[v], cov[v], ccv[v], Tv[v], dvv[v], g_b1, O1v[v]);
        cudaEventRecord(ev[EV_O1_0 + v], s1);
    }
    for (int v = 0; v < 2; v++) {
        cudaStreamWaitEvent(0, ev[EV_O1_0 + v], 0);
        hgemm_k<0,1,1><<<dim3(HD / 128, 125), 256, SMEM_BYTES>>>(
            16000, HD, HD, O1v[v], GW2t, Tv[v], HD, nullptr, dvv[v]);
        cudaEventRecord(ev[EV_T2_0 + v], 0);
    }
    for (int v = 0; v < 2; v++) {
        cudaStreamWaitEvent(s1, ev[EV_T2_0 + v], 0);
        spagg_k<HD,1,1><<<dim3(NN, 8), HD/2, 0, s1>>>(vv[v], rv2[v], cov[v], ccv[v], Tv[v], dvv[v], g_b2, O2v[v]);
        cudaEventRecord(ev[EV_O2_0 + v], s1);
    }
    for (int v = 0; v < 2; v++) {
        cudaStreamWaitEvent(0, ev[EV_O2_0 + v], 0);
        hgemm_k<0,1,1><<<dim3(1, 125), 256, SMEM_BYTES>>>(
            16000, D_, HD, O2v[v], GW3t, Tv[v], D_, nullptr, dvv[v]);
        cudaEventRecord(ev[EV_T3_0 + v], 0);
    }
    for (int v = 0; v < 2; v++) {
        cudaStreamWaitEvent(s1, ev[EV_T3_0 + v], 0);
        spagg_k<D_,0,0><<<dim3(NN, 8), D_/2, 0, s1>>>(vv[v], rv2[v], cov[v], ccv[v], Tv[v], dvv[v], g_b3, O3v[v]);
        meanz1_k<<<8, 128, 0, s1>>>(O3v[v], epsA[v], muo[v], stdo[v], zb + v * 512);
        decode_k<<<dim3(8, 8), 256, 0, s1>>>(zb + v * 512, dW1[v], dB1[v], dG[v], dBe[v],
                                             dW2[v], dB2[v], xrec[v]);
    }

    // ---- join ----
    cudaEventRecord(ev[EV_JOIN], s1);
    cudaStreamWaitEvent(0, ev[EV_JOIN], 0);
}